// round 15
// baseline (speedup 1.0000x reference)
#include <cuda_runtime.h>
#include <cuda_bf16.h>
#include <stdint.h>

#define BB 16384
#define D_SUP 1024
#define D_ANOM 128
#define D_IND 2048
#define D_IN 3200
#define H1 256
#define FEAT 128
#define DEPTH 12
#define NCOND 14
#define CAP 256

__device__ __nv_bfloat16 g_Wh1[H1 * D_IN];
__device__ __nv_bfloat16 g_Wl1[H1 * D_IN];
__device__ __nv_bfloat16 g_Wh2[FEAT * H1];
__device__ __nv_bfloat16 g_Wl2[FEAT * H1];
__device__ __nv_bfloat16 g_WhC[DEPTH * FEAT * FEAT];
__device__ __nv_bfloat16 g_WlC[DEPTH * FEAT * FEAT];
__device__ __nv_bfloat16 g_h1h[BB * H1];
__device__ __nv_bfloat16 g_h1l[BB * H1];
__device__ __nv_bfloat16 g_WfinH[NCOND * 256 * FEAT];
__device__ __nv_bfloat16 g_WfinL[NCOND * 256 * FEAT];
__device__ float g_MkF[NCOND * FEAT * FEAT];
__device__ float g_aw[BB];

__device__ __forceinline__ uint32_t smem_u32(const void* p) {
    uint32_t a;
    asm("{ .reg .u64 t; cvta.to.shared.u64 t, %1; cvt.u32.u64 %0, t; }" : "=r"(a) : "l"(p));
    return a;
}
__device__ __forceinline__ void ldsm4(uint32_t* r, uint32_t addr) {
    asm volatile("ldmatrix.sync.aligned.m8n8.x4.shared.b16 {%0,%1,%2,%3}, [%4];"
                 : "=r"(r[0]), "=r"(r[1]), "=r"(r[2]), "=r"(r[3]) : "r"(addr));
}
__device__ __forceinline__ void ldsm2(uint32_t* r, uint32_t addr) {
    asm volatile("ldmatrix.sync.aligned.m8n8.x2.shared.b16 {%0,%1}, [%2];"
                 : "=r"(r[0]), "=r"(r[1]) : "r"(addr));
}
__device__ __forceinline__ void mma_bf16(float* c, const uint32_t* a, const uint32_t* b) {
    asm volatile("mma.sync.aligned.m16n8k16.row.col.f32.bf16.bf16.f32 "
                 "{%0,%1,%2,%3}, {%4,%5,%6,%7}, {%8,%9}, {%0,%1,%2,%3};"
                 : "+f"(c[0]), "+f"(c[1]), "+f"(c[2]), "+f"(c[3])
                 : "r"(a[0]), "r"(a[1]), "r"(a[2]), "r"(a[3]), "r"(b[0]), "r"(b[1]));
}
__device__ __forceinline__ void cp16(uint32_t smem, const void* g) {
    asm volatile("cp.async.cg.shared.global [%0], [%1], 16;" :: "r"(smem), "l"(g));
}
#define CP_COMMIT() asm volatile("cp.async.commit_group;" ::: "memory")
#define CP_WAIT0()  asm volatile("cp.async.wait_group 0;" ::: "memory")

__global__ __launch_bounds__(256) void aw_kernel(const float* __restrict__ anom,
                                                 float* __restrict__ aw) {
    int warp = (blockIdx.x * blockDim.x + threadIdx.x) >> 5;
    int lane = threadIdx.x & 31;
    if (warp >= BB) return;
    float4 v = *(const float4*)(anom + (size_t)warp * D_ANOM + lane * 4);
    float s = fabsf(v.x) + fabsf(v.y) + fabsf(v.z) + fabsf(v.w);
    #pragma unroll
    for (int o = 16; o; o >>= 1) s += __shfl_xor_sync(0xFFFFFFFFu, s, o);
    if (lane == 0) aw[warp] = s * (1.0f / D_ANOM);
}

__global__ __launch_bounds__(256) void mkzero_kernel(float* __restrict__ MkF) {
    int i = blockIdx.x * 256 + threadIdx.x;
    *(float4*)(MkF + (size_t)i * 4) = make_float4(0.f, 0.f, 0.f, 0.f);
}

__global__ __launch_bounds__(256) void mkpart_kernel(const float* __restrict__ refp,
                                                     const float* __restrict__ objp,
                                                     float* __restrict__ MkF) {
    const int k = blockIdx.x;
    const int cbase = blockIdx.y * 64;
    __shared__ float Rs[32][FEAT];
    __shared__ float Os[32][FEAT];
    const int tid = threadIdx.x;
    const int tc = tid & 15;
    const int tr = tid >> 4;
    float acc[8][8] = {};
    const float* rb = refp + (size_t)k * CAP * FEAT;
    const float* ob = objp + (size_t)k * CAP * FEAT;
    for (int cc = 0; cc < 64; cc += 32) {
        const int c0 = cbase + cc;
        #pragma unroll
        for (int i = tid; i < 32 * FEAT / 4; i += 256) {
            int c = i >> 5, d4 = (i & 31) * 4;
            *(float4*)&Rs[c][d4] = *(const float4*)(rb + (size_t)(c0 + c) * FEAT + d4);
            *(float4*)&Os[c][d4] = *(const float4*)(ob + (size_t)(c0 + c) * FEAT + d4);
        }
        __syncthreads();
        #pragma unroll 8
        for (int c = 0; c < 32; c++) {
            float a[8], b[8];
            #pragma unroll
            for (int i = 0; i < 8; i += 4) *(float4*)&a[i] = *(const float4*)&Rs[c][tr * 8 + i];
            #pragma unroll
            for (int j = 0; j < 8; j += 4) *(float4*)&b[j] = *(const float4*)&Os[c][tc * 8 + j];
            #pragma unroll
            for (int i = 0; i < 8; i++)
                #pragma unroll
                for (int j = 0; j < 8; j++) acc[i][j] += a[i] * b[j];
        }
        __syncthreads();
    }
    float* mb = MkF + (size_t)k * FEAT * FEAT;
    #pragma unroll
    for (int i = 0; i < 8; i++)
        #pragma unroll
        for (int j = 0; j < 8; j++)
            atomicAdd(mb + (size_t)(tr * 8 + i) * FEAT + tc * 8 + j, acc[i][j]);
}

__global__ __launch_bounds__(256) void mkcvt_kernel(const float* __restrict__ MkF,
                                                    __nv_bfloat16* __restrict__ WfH,
                                                    __nv_bfloat16* __restrict__ WfL) {
    const int k = blockIdx.x;
    const float* mb = MkF + (size_t)k * FEAT * FEAT;
    for (int idx = threadIdx.x; idx < FEAT * FEAT; idx += 256) {
        int e = idx >> 7, d = idx & 127;
        float v = mb[(size_t)d * FEAT + e];
        __nv_bfloat16 hi = __float2bfloat16(v);
        __nv_bfloat16 lo = __float2bfloat16(v - __bfloat162float(hi));
        size_t dst = (size_t)k * 256 * FEAT + (size_t)(128 + e) * FEAT + d;
        WfH[dst] = hi;
        WfL[dst] = lo;
    }
}

__global__ __launch_bounds__(256) void tsplit_kernel(const float* __restrict__ W,
                                                     __nv_bfloat16* __restrict__ Wh,
                                                     __nv_bfloat16* __restrict__ Wl,
                                                     int K, int N, int dstBatchStride) {
    const int batch = blockIdx.z;
    W += (size_t)batch * K * N;
    Wh += (size_t)batch * dstBatchStride;
    Wl += (size_t)batch * dstBatchStride;
    __shared__ float t[32][33];
    const int k0 = blockIdx.x * 32;
    const int n0 = blockIdx.y * 32;
    const int tx = threadIdx.x, ty = threadIdx.y;
    #pragma unroll
    for (int i = 0; i < 4; i++)
        t[ty + 8 * i][tx] = W[(size_t)(k0 + ty + 8 * i) * N + n0 + tx];
    __syncthreads();
    #pragma unroll
    for (int i = 0; i < 4; i++) {
        int n = n0 + ty + 8 * i;
        int k = k0 + tx;
        float v = t[tx][ty + 8 * i];
        __nv_bfloat16 hi = __float2bfloat16(v);
        __nv_bfloat16 lo = __float2bfloat16(v - __bfloat162float(hi));
        Wh[(size_t)n * K + k] = hi;
        Wl[(size_t)n * K + k] = lo;
    }
}

// ===========================================================================
// GEMM1 v5 (unchanged): BM=64, BN=64, 4 CTAs/SM, 1024 CTAs.
// ===========================================================================
#define G5_OA  0
#define G5_OWH 10240
#define G5_OWL 15360
#define G5_BUF 20480
#define G5_SMEM (2 * G5_BUF)
#define G5_NIT (D_IN / 32)

__global__ __launch_bounds__(256, 4) void gemm1_v5(
    const float* __restrict__ A0, const float* __restrict__ A1,
    const float* __restrict__ A2,
    const __nv_bfloat16* __restrict__ Bh, const __nv_bfloat16* __restrict__ Bl,
    const float* __restrict__ bias,
    __nv_bfloat16* __restrict__ Oh, __nv_bfloat16* __restrict__ Ol) {
    extern __shared__ char sm[];
    const uint32_t sb = smem_u32(sm);
    const int tid = threadIdx.x;
    const int wid = tid >> 5, lane = tid & 31;
    const int warpM = (wid & 1) * 32;
    const int warpN = (wid >> 1) * 16;
    const int n0 = blockIdx.x * 64;
    const int m0 = blockIdx.y * 64;

    float acc[2][2][4];
    #pragma unroll
    for (int i = 0; i < 2; i++)
        #pragma unroll
        for (int j = 0; j < 2; j++)
            #pragma unroll
            for (int q = 0; q < 4; q++) acc[i][j][q] = 0.f;

    auto issue = [&](int it, int b) {
        const int k0 = it * 32;
        const float* Ap; int lda, kk;
        if (k0 < D_SUP)               { Ap = A0; lda = D_SUP;  kk = k0; }
        else if (k0 < D_SUP + D_ANOM) { Ap = A1; lda = D_ANOM; kk = k0 - D_SUP; }
        else                          { Ap = A2; lda = D_IND;  kk = k0 - D_SUP - D_ANOM; }
        const uint32_t bb = sb + b * G5_BUF;
        #pragma unroll
        for (int t = 0; t < 2; t++) {
            int idx = tid + t * 256;
            int row = idx >> 3, q = idx & 7;
            cp16(bb + G5_OA + row * 144 + q * 16,
                 Ap + (size_t)(m0 + row) * lda + kk + q * 4);
        }
        #pragma unroll
        for (int t = 0; t < 2; t++) {
            int idx = tid + t * 256;
            int plane = idx >= 256;
            int cc = idx & 255;
            int row = cc >> 2, q = cc & 3;
            cp16(bb + (plane ? G5_OWL : G5_OWH) + row * 80 + q * 16,
                 (plane ? Bl : Bh) + (size_t)(n0 + row) * D_IN + k0 + q * 8);
        }
        CP_COMMIT();
    };

    issue(0, 0);

    for (int it = 0; it < G5_NIT; it++) {
        const int b = it & 1;
        const uint32_t bb = sb + b * G5_BUF;
        CP_WAIT0();
        __syncthreads();
        if (it + 1 < G5_NIT) issue(it + 1, b ^ 1);

        float4 v[2];
        #pragma unroll
        for (int t = 0; t < 2; t++) {
            int idx = tid + t * 256;
            int row = idx >> 3, q = idx & 7;
            v[t] = *(const float4*)(sm + (size_t)b * G5_BUF + G5_OA + row * 144 + q * 16);
        }
        __syncthreads();
        #pragma unroll
        for (int t = 0; t < 2; t++) {
            int idx = tid + t * 256;
            int row = idx >> 3, q = idx & 7;
            __nv_bfloat16 hx = __float2bfloat16(v[t].x), hy = __float2bfloat16(v[t].y);
            __nv_bfloat16 hz = __float2bfloat16(v[t].z), hw = __float2bfloat16(v[t].w);
            __nv_bfloat162 h01 = {hx, hy}, h23 = {hz, hw};
            __nv_bfloat162 l01 = __floats2bfloat162_rn(v[t].x - __bfloat162float(hx),
                                                       v[t].y - __bfloat162float(hy));
            __nv_bfloat162 l23 = __floats2bfloat162_rn(v[t].z - __bfloat162float(hz),
                                                       v[t].w - __bfloat162float(hw));
            size_t off = (size_t)b * G5_BUF + G5_OA + row * 80 + q * 8;
            *(__nv_bfloat162*)(sm + off) = h01;
            *(__nv_bfloat162*)(sm + off + 4) = h23;
            *(__nv_bfloat162*)(sm + off + 5120) = l01;
            *(__nv_bfloat162*)(sm + off + 5120 + 4) = l23;
        }
        __syncthreads();

        #pragma unroll
        for (int kq = 0; kq < 2; kq++) {
            const uint32_t colb = (uint32_t)(kq * 16 + ((lane >> 4) << 3)) * 2;
            uint32_t a_h[2][4], a_l[2][4], bh[2][2], bl[2][2];
            #pragma unroll
            for (int mt = 0; mt < 2; mt++) {
                uint32_t off = (uint32_t)(warpM + mt * 16 + (lane & 15)) * 80 + colb;
                ldsm4(a_h[mt], bb + G5_OA + off);
                ldsm4(a_l[mt], bb + G5_OA + 5120 + off);
            }
            {
                uint32_t off = (uint32_t)(warpN + (lane & 15)) * 80 + colb;
                uint32_t r[4];
                ldsm4(r, bb + G5_OWH + off);
                bh[0][0] = r[0]; bh[0][1] = r[2];
                bh[1][0] = r[1]; bh[1][1] = r[3];
                ldsm4(r, bb + G5_OWL + off);
                bl[0][0] = r[0]; bl[0][1] = r[2];
                bl[1][0] = r[1]; bl[1][1] = r[3];
            }
            #pragma unroll
            for (int mt = 0; mt < 2; mt++)
                #pragma unroll
                for (int nt = 0; nt < 2; nt++) mma_bf16(acc[mt][nt], a_h[mt], bh[nt]);
            #pragma unroll
            for (int mt = 0; mt < 2; mt++)
                #pragma unroll
                for (int nt = 0; nt < 2; nt++) mma_bf16(acc[mt][nt], a_l[mt], bh[nt]);
            #pragma unroll
            for (int mt = 0; mt < 2; mt++)
                #pragma unroll
                for (int nt = 0; nt < 2; nt++) mma_bf16(acc[mt][nt], a_h[mt], bl[nt]);
        }
    }

    #pragma unroll
    for (int mt = 0; mt < 2; mt++) {
        const int r0 = m0 + warpM + mt * 16 + (lane >> 2);
        #pragma unroll
        for (int nt = 0; nt < 2; nt++) {
            const int ng = n0 + warpN + nt * 8 + ((lane & 3) << 1);
            float2 bv = *(const float2*)(bias + ng);
            float v00 = fmaxf(acc[mt][nt][0] + bv.x, 0.f);
            float v01 = fmaxf(acc[mt][nt][1] + bv.y, 0.f);
            float v10 = fmaxf(acc[mt][nt][2] + bv.x, 0.f);
            float v11 = fmaxf(acc[mt][nt][3] + bv.y, 0.f);
            __nv_bfloat16 h00 = __float2bfloat16(v00), h01 = __float2bfloat16(v01);
            __nv_bfloat16 h10 = __float2bfloat16(v10), h11 = __float2bfloat16(v11);
            __nv_bfloat162 hi0 = {h00, h01}, hi1 = {h10, h11};
            __nv_bfloat162 lo0 = __floats2bfloat162_rn(v00 - __bfloat162float(h00),
                                                       v01 - __bfloat162float(h01));
            __nv_bfloat162 lo1 = __floats2bfloat162_rn(v10 - __bfloat162float(h10),
                                                       v11 - __bfloat162float(h11));
            *(__nv_bfloat162*)(Oh + (size_t)r0 * H1 + ng) = hi0;
            *(__nv_bfloat162*)(Ol + (size_t)r0 * H1 + ng) = lo0;
            *(__nv_bfloat162*)(Oh + (size_t)(r0 + 8) * H1 + ng) = hi1;
            *(__nv_bfloat162*)(Ol + (size_t)(r0 + 8) * H1 + ng) = lo1;
        }
    }
}

// ===========================================================================
// Fused tail v5: 256 CTAs x 512 threads, 64-row act, 64-row W chunks, 2/SM.
// ===========================================================================
#define LDA 136
#define T5_SMEM (64 * LDA * 2 * 2 * 2 + 128 * 4)

__global__ __launch_bounds__(512, 2) void fused_tail5(
    const __nv_bfloat16* __restrict__ h1h, const __nv_bfloat16* __restrict__ h1l,
    const __nv_bfloat16* __restrict__ Wh2, const __nv_bfloat16* __restrict__ Wl2,
    const float* __restrict__ b2,
    const __nv_bfloat16* __restrict__ WhC, const __nv_bfloat16* __restrict__ WlC,
    const float* __restrict__ consB,
    const __nv_bfloat16* __restrict__ WfH, const __nv_bfloat16* __restrict__ WfL,
    const float* __restrict__ retB, const float* __restrict__ aw,
    float* __restrict__ out) {
    extern __shared__ __nv_bfloat16 smt[];
    __nv_bfloat16* sAh = smt;
    __nv_bfloat16* sAl = sAh + 64 * LDA;
    __nv_bfloat16* sWh = sAl + 64 * LDA;
    __nv_bfloat16* sWl = sWh + 64 * LDA;
    float* wsum = (float*)(sWl + 64 * LDA);
    float* saw  = wsum + 64;

    const int tid = threadIdx.x;
    const int wid = tid >> 5, lane = tid & 31;
    const int wm = wid & 1;
    const int wn = wid >> 1;                  // 0..7
    const int m0 = blockIdx.x * 64;

    const uint32_t aAh = smem_u32(sAh), aAl = smem_u32(sAl);
    const uint32_t aWh = smem_u32(sWh), aWl = smem_u32(sWl);

    auto loadW64 = [&](const __nv_bfloat16* srcH, const __nv_bfloat16* srcL,
                       int srcStride, int colOff, int rowOff) {
        #pragma unroll
        for (int t = 0; t < 4; t++) {
            int idx = tid + t * 512;
            int half = idx >= 1024;
            int cc = idx & 1023;
            int row = cc >> 4, q = cc & 15;
            const __nv_bfloat16* src = (half ? srcL : srcH)
                + (size_t)(rowOff + row) * srcStride + colOff + q * 8;
            cp16((half ? aWl : aWh) + (uint32_t)(row * LDA + q * 8) * 2, src);
        }
        CP_COMMIT();
    };
    auto loadAct = [&](int kc) {
        #pragma unroll
        for (int t = 0; t < 4; t++) {
            int idx = tid + t * 512;
            int half = idx >= 1024;
            int cc = idx & 1023;
            int row = cc >> 4, q = cc & 15;
            const __nv_bfloat16* src = (half ? h1l : h1h)
                + (size_t)(m0 + row) * H1 + kc * 128 + q * 8;
            cp16((half ? aAl : aAh) + (uint32_t)(row * LDA + q * 8) * 2, src);
        }
        CP_COMMIT();
    };

    auto mma64 = [&](float acc[2][4]) {
        const int l8 = lane & 7;
        const int sel = (lane >> 3) & 1;
        #pragma unroll
        for (int ch = 0; ch < 8; ch++) {
            const int colh = ch * 16 + ((lane >> 4) << 3);
            uint32_t a_h[2][4], a_l[2][4], bh[2], bl[2];
            #pragma unroll
            for (int mt = 0; mt < 2; mt++) {
                int row = wm * 32 + mt * 16 + (lane & 15);
                ldsm4(a_h[mt], aAh + (uint32_t)(row * LDA + colh) * 2);
                ldsm4(a_l[mt], aAl + (uint32_t)(row * LDA + colh) * 2);
            }
            const int brow = wn * 8 + l8;
            const int bcol = ch * 16 + sel * 8;
            ldsm2(bh, aWh + (uint32_t)(brow * LDA + bcol) * 2);
            ldsm2(bl, aWl + (uint32_t)(brow * LDA + bcol) * 2);
            #pragma unroll
            for (int mt = 0; mt < 2; mt++) mma_bf16(acc[mt], a_h[mt], bh);
            #pragma unroll
            for (int mt = 0; mt < 2; mt++) mma_bf16(acc[mt], a_l[mt], bh);
            #pragma unroll
            for (int mt = 0; mt < 2; mt++) mma_bf16(acc[mt], a_h[mt], bl);
        }
    };
    auto epi64 = [&](float acc[2][4], const float* biasp, int colBase) {
        #pragma unroll
        for (int mt = 0; mt < 2; mt++) {
            const int row = wm * 32 + mt * 16 + (lane >> 2);
            const int col = colBase + wn * 8 + ((lane & 3) << 1);
            float2 bv = *(const float2*)(biasp + col);
            float v00 = fmaxf(acc[mt][0] + bv.x, 0.f);
            float v01 = fmaxf(acc[mt][1] + bv.y, 0.f);
            float v10 = fmaxf(acc[mt][2] + bv.x, 0.f);
            float v11 = fmaxf(acc[mt][3] + bv.y, 0.f);
            __nv_bfloat16 h00 = __float2bfloat16(v00), h01 = __float2bfloat16(v01);
            __nv_bfloat16 h10 = __float2bfloat16(v10), h11 = __float2bfloat16(v11);
            __nv_bfloat162 hi0 = {h00, h01}, hi1 = {h10, h11};
            __nv_bfloat162 lo0 = __floats2bfloat162_rn(v00 - __bfloat162float(h00),
                                                       v01 - __bfloat162float(h01));
            __nv_bfloat162 lo1 = __floats2bfloat162_rn(v10 - __bfloat162float(h10),
                                                       v11 - __bfloat162float(h11));
            *(__nv_bfloat162*)(sAh + row * LDA + col) = hi0;
            *(__nv_bfloat162*)(sAl + row * LDA + col) = lo0;
            *(__nv_bfloat162*)(sAh + (row + 8) * LDA + col) = hi1;
            *(__nv_bfloat162*)(sAl + (row + 8) * LDA + col) = lo1;
        }
    };

    if (tid < 64) saw[tid] = aw[m0 + tid];

    float acc0[2][4], acc1[2][4];
    #pragma unroll
    for (int i = 0; i < 2; i++)
        #pragma unroll
        for (int q = 0; q < 4; q++) { acc0[i][q] = 0.f; acc1[i][q] = 0.f; }

    // GEMM2: K=256 chunks x N=128 halves
    for (int kc = 0; kc < 2; kc++) {
        loadAct(kc);
        loadW64(Wh2, Wl2, H1, kc * 128, 0);
        CP_WAIT0();
        __syncthreads();
        mma64(acc0);
        __syncthreads();
        loadW64(Wh2, Wl2, H1, kc * 128, 64);
        CP_WAIT0();
        __syncthreads();
        mma64(acc1);
        __syncthreads();
    }
    epi64(acc0, b2, 0);
    epi64(acc1, b2, 64);
    __syncthreads();

    // 12 consolidator layers
    for (int l = 0; l < DEPTH; l++) {
        const __nv_bfloat16* wh = WhC + (size_t)l * FEAT * FEAT;
        const __nv_bfloat16* wl = WlC + (size_t)l * FEAT * FEAT;
        #pragma unroll
        for (int i = 0; i < 2; i++)
            #pragma unroll
            for (int q = 0; q < 4; q++) { acc0[i][q] = 0.f; acc1[i][q] = 0.f; }
        loadW64(wh, wl, FEAT, 0, 0);
        CP_WAIT0();
        __syncthreads();
        mma64(acc0);
        __syncthreads();
        loadW64(wh, wl, FEAT, 0, 64);
        CP_WAIT0();
        __syncthreads();
        mma64(acc1);
        __syncthreads();
        epi64(acc0, consB + (size_t)l * FEAT, 0);
        epi64(acc1, consB + (size_t)l * FEAT, 64);
        __syncthreads();
    }

    // final retrieval
    const float cfac = 0.42f * 1.8f / (float)CAP;
    for (int k = 0; k < NCOND; k++) {
        const __nv_bfloat16* fh = WfH + (size_t)k * 256 * FEAT;
        const __nv_bfloat16* fl = WfL + (size_t)k * 256 * FEAT;
        if (tid < 64) wsum[tid] = 0.f;

        float accT0[2][4], accT1[2][4];
        #pragma unroll
        for (int i = 0; i < 2; i++)
            #pragma unroll
            for (int q = 0; q < 4; q++) { accT0[i][q] = 0.f; accT1[i][q] = 0.f; }

        loadW64(fh, fl, FEAT, 0, 128);
        CP_WAIT0();
        __syncthreads();
        mma64(accT0);
        __syncthreads();
        loadW64(fh, fl, FEAT, 0, 192);
        CP_WAIT0();
        __syncthreads();
        mma64(accT1);
        __syncthreads();

        #pragma unroll
        for (int mt = 0; mt < 2; mt++) {
            const int r1 = wm * 32 + mt * 16 + (lane >> 2);
            const int e0 = wn * 8 + ((lane & 3) << 1);
            float m00 = __bfloat162float(sAh[r1 * LDA + e0]) + __bfloat162float(sAl[r1 * LDA + e0]);
            float m01 = __bfloat162float(sAh[r1 * LDA + e0 + 1]) + __bfloat162float(sAl[r1 * LDA + e0 + 1]);
            float m10 = __bfloat162float(sAh[(r1 + 8) * LDA + e0]) + __bfloat162float(sAl[(r1 + 8) * LDA + e0]);
            float m11 = __bfloat162float(sAh[(r1 + 8) * LDA + e0 + 1]) + __bfloat162float(sAl[(r1 + 8) * LDA + e0 + 1]);
            float n00 = __bfloat162float(sAh[r1 * LDA + 64 + e0]) + __bfloat162float(sAl[r1 * LDA + 64 + e0]);
            float n01 = __bfloat162float(sAh[r1 * LDA + 64 + e0 + 1]) + __bfloat162float(sAl[r1 * LDA + 64 + e0 + 1]);
            float n10 = __bfloat162float(sAh[(r1 + 8) * LDA + 64 + e0]) + __bfloat162float(sAl[(r1 + 8) * LDA + 64 + e0]);
            float n11 = __bfloat162float(sAh[(r1 + 8) * LDA + 64 + e0 + 1]) + __bfloat162float(sAl[(r1 + 8) * LDA + 64 + e0 + 1]);
            float p1 = accT0[mt][0] * m00 + accT0[mt][1] * m01 + accT1[mt][0] * n00 + accT1[mt][1] * n01;
            float p2 = accT0[mt][2] * m10 + accT0[mt][3] * m11 + accT1[mt][2] * n10 + accT1[mt][3] * n11;
            atomicAdd(&wsum[r1], p1);
            atomicAdd(&wsum[r1 + 8], p2);
        }
        __syncthreads();
        if (tid < 64) wsum[tid] = wsum[tid] * cfac + 0.3f * saw[tid];
        __syncthreads();

        #pragma unroll
        for (int half = 0; half < 2; half++) {
            float accR[2][4];
            #pragma unroll
            for (int i = 0; i < 2; i++)
                #pragma unroll
                for (int q = 0; q < 4; q++) accR[i][q] = 0.f;
            loadW64(fh, fl, FEAT, 0, half * 64);
            CP_WAIT0();
            __syncthreads();
            mma64(accR);
            #pragma unroll
            for (int mt = 0; mt < 2; mt++) {
                const int rl = wm * 32 + mt * 16 + (lane >> 2);
                const float w1 = wsum[rl], w2 = wsum[rl + 8];
                const int col = half * 64 + wn * 8 + ((lane & 3) << 1);
                float2 bv = *(const float2*)(retB + (size_t)k * FEAT + col);
                size_t base1 = (size_t)(m0 + rl) * (NCOND * FEAT) + (size_t)k * FEAT + col;
                size_t base2 = (size_t)(m0 + rl + 8) * (NCOND * FEAT) + (size_t)k * FEAT + col;
                *(float2*)(out + base1) = make_float2((accR[mt][0] + bv.x) * w1,
                                                      (accR[mt][1] + bv.y) * w1);
                *(float2*)(out + base2) = make_float2((accR[mt][2] + bv.x) * w2,
                                                      (accR[mt][3] + bv.y) * w2);
            }
            __syncthreads();
        }
    }
}

// ===========================================================================
extern "C" void kernel_launch(void* const* d_in, const int* in_sizes, int n_in,
                              void* d_out, int out_size) {
    const float* sup  = (const float*)d_in[0];
    const float* anom = (const float*)d_in[1];
    const float* ind  = (const float*)d_in[2];
    const float* ipW1 = (const float*)d_in[3];
    const float* ipb1 = (const float*)d_in[4];
    const float* ipW2 = (const float*)d_in[5];
    const float* ipb2 = (const float*)d_in[6];
    const float* consW = (const float*)d_in[7];
    const float* consB = (const float*)d_in[8];
    const float* refp = (const float*)d_in[9];
    const float* objp = (const float*)d_in[10];
    const float* retW = (const float*)d_in[11];
    const float* retB = (const float*)d_in[12];
    float* out = (float*)d_out;

    __nv_bfloat16 *Wh1, *Wl1, *Wh2, *Wl2, *WhC, *WlC, *h1h, *h1l, *WfH, *WfL;
    float *aw, *MkF;
    cudaGetSymbolAddress((void**)&Wh1, g_Wh1);
    cudaGetSymbolAddress((void**)&Wl1, g_Wl1);
    cudaGetSymbolAddress((void**)&Wh2, g_Wh2);
    cudaGetSymbolAddress((void**)&Wl2, g_Wl2);
    cudaGetSymbolAddress((void**)&WhC, g_WhC);
    cudaGetSymbolAddress((void**)&WlC, g_WlC);
    cudaGetSymbolAddress((void**)&h1h, g_h1h);
    cudaGetSymbolAddress((void**)&h1l, g_h1l);
    cudaGetSymbolAddress((void**)&WfH, g_WfinH);
    cudaGetSymbolAddress((void**)&WfL, g_WfinL);
    cudaGetSymbolAddress((void**)&aw, g_aw);
    cudaGetSymbolAddress((void**)&MkF, g_MkF);

    cudaFuncSetAttribute(gemm1_v5, cudaFuncAttributeMaxDynamicSharedMemorySize, G5_SMEM);
    cudaFuncSetAttribute(fused_tail5, cudaFuncAttributeMaxDynamicSharedMemorySize, T5_SMEM);

    tsplit_kernel<<<dim3(D_IN / 32, H1 / 32, 1), dim3(32, 8)>>>(ipW1, Wh1, Wl1, D_IN, H1, H1 * D_IN); // 1
    aw_kernel<<<BB * 32 / 256, 256>>>(anom, aw);                                      // 2
    mkzero_kernel<<<NCOND * FEAT * FEAT / 1024, 256>>>(MkF);                          // 3
    gemm1_v5<<<dim3(4, BB / 64), 256, G5_SMEM>>>(sup, anom, ind, Wh1, Wl1, ipb1, h1h, h1l); // 4 (profiled)
    mkpart_kernel<<<dim3(NCOND, 4), 256>>>(refp, objp, MkF);                          // 5
    mkcvt_kernel<<<NCOND, 256>>>(MkF, WfH, WfL);                                      // 6
    tsplit_kernel<<<dim3(H1 / 32, FEAT / 32, 1), dim3(32, 8)>>>(ipW2, Wh2, Wl2, H1, FEAT, FEAT * H1); // 7
    tsplit_kernel<<<dim3(FEAT / 32, FEAT / 32, DEPTH), dim3(32, 8)>>>(consW, WhC, WlC, FEAT, FEAT, FEAT * FEAT); // 8
    tsplit_kernel<<<dim3(FEAT / 32, FEAT / 32, NCOND), dim3(32, 8)>>>(retW, WfH, WfL, FEAT, FEAT, 256 * FEAT);   // 9
    fused_tail5<<<BB / 64, 512, T5_SMEM>>>(
        h1h, h1l, Wh2, Wl2, ipb2, WhC, WlC, consB, WfH, WfL, retB, aw, out);          // 10
}

// round 16
// speedup vs baseline: 1.1988x; 1.1988x over previous
#include <cuda_runtime.h>
#include <cuda_bf16.h>
#include <stdint.h>

#define BB 16384
#define D_SUP 1024
#define D_ANOM 128
#define D_IND 2048
#define D_IN 3200
#define H1 256
#define FEAT 128
#define DEPTH 12
#define NCOND 14
#define CAP 256

// ---------------- scratch (device globals; no allocation allowed) ----------
__device__ __nv_bfloat16 g_Wh1[H1 * D_IN];
__device__ __nv_bfloat16 g_Wl1[H1 * D_IN];
__device__ __nv_bfloat16 g_Wh2[FEAT * H1];
__device__ __nv_bfloat16 g_Wl2[FEAT * H1];
__device__ __nv_bfloat16 g_WhC[DEPTH * FEAT * FEAT];
__device__ __nv_bfloat16 g_WlC[DEPTH * FEAT * FEAT];
__device__ __nv_bfloat16 g_h1h[BB * H1];
__device__ __nv_bfloat16 g_h1l[BB * H1];
__device__ __nv_bfloat16 g_WfinH[NCOND * 256 * FEAT]; // rows 0-127 retW^T, 128-255 Mk^T
__device__ __nv_bfloat16 g_WfinL[NCOND * 256 * FEAT];
__device__ float g_MkF[NCOND * FEAT * FEAT];
__device__ float g_aw[BB];

// ---------------- helpers --------------------------------------------------
__device__ __forceinline__ uint32_t smem_u32(const void* p) {
    uint32_t a;
    asm("{ .reg .u64 t; cvta.to.shared.u64 t, %1; cvt.u32.u64 %0, t; }" : "=r"(a) : "l"(p));
    return a;
}
__device__ __forceinline__ void ldsm4(uint32_t* r, uint32_t addr) {
    asm volatile("ldmatrix.sync.aligned.m8n8.x4.shared.b16 {%0,%1,%2,%3}, [%4];"
                 : "=r"(r[0]), "=r"(r[1]), "=r"(r[2]), "=r"(r[3]) : "r"(addr));
}
__device__ __forceinline__ void mma_bf16(float* c, const uint32_t* a, const uint32_t* b) {
    asm volatile("mma.sync.aligned.m16n8k16.row.col.f32.bf16.bf16.f32 "
                 "{%0,%1,%2,%3}, {%4,%5,%6,%7}, {%8,%9}, {%0,%1,%2,%3};"
                 : "+f"(c[0]), "+f"(c[1]), "+f"(c[2]), "+f"(c[3])
                 : "r"(a[0]), "r"(a[1]), "r"(a[2]), "r"(a[3]), "r"(b[0]), "r"(b[1]));
}
__device__ __forceinline__ void cp16(uint32_t smem, const void* g) {
    asm volatile("cp.async.cg.shared.global [%0], [%1], 16;" :: "r"(smem), "l"(g));
}
#define CP_COMMIT() asm volatile("cp.async.commit_group;" ::: "memory")
#define CP_WAIT0()  asm volatile("cp.async.wait_group 0;" ::: "memory")
#define CP_WAIT1()  asm volatile("cp.async.wait_group 1;" ::: "memory")

// ---------------- aw[b] = mean(|anomaly[b,:]|) -----------------------------
__global__ __launch_bounds__(256) void aw_kernel(const float* __restrict__ anom,
                                                 float* __restrict__ aw) {
    int warp = (blockIdx.x * blockDim.x + threadIdx.x) >> 5;
    int lane = threadIdx.x & 31;
    if (warp >= BB) return;
    float4 v = *(const float4*)(anom + (size_t)warp * D_ANOM + lane * 4);
    float s = fabsf(v.x) + fabsf(v.y) + fabsf(v.z) + fabsf(v.w);
    #pragma unroll
    for (int o = 16; o; o >>= 1) s += __shfl_xor_sync(0xFFFFFFFFu, s, o);
    if (lane == 0) aw[warp] = s * (1.0f / D_ANOM);
}

// ---------------- zero fp32 Mk staging -------------------------------------
__global__ __launch_bounds__(256) void mkzero_kernel(float* __restrict__ MkF) {
    int i = blockIdx.x * 256 + threadIdx.x;
    *(float4*)(MkF + (size_t)i * 4) = make_float4(0.f, 0.f, 0.f, 0.f);
}

// ---------------- Mk partial: grid (14, 4) ---------------------------------
__global__ __launch_bounds__(256) void mkpart_kernel(const float* __restrict__ refp,
                                                     const float* __restrict__ objp,
                                                     float* __restrict__ MkF) {
    const int k = blockIdx.x;
    const int cbase = blockIdx.y * 64;
    __shared__ float Rs[32][FEAT];
    __shared__ float Os[32][FEAT];
    const int tid = threadIdx.x;
    const int tc = tid & 15;
    const int tr = tid >> 4;
    float acc[8][8] = {};
    const float* rb = refp + (size_t)k * CAP * FEAT;
    const float* ob = objp + (size_t)k * CAP * FEAT;
    for (int cc = 0; cc < 64; cc += 32) {
        const int c0 = cbase + cc;
        #pragma unroll
        for (int i = tid; i < 32 * FEAT / 4; i += 256) {
            int c = i >> 5, d4 = (i & 31) * 4;
            *(float4*)&Rs[c][d4] = *(const float4*)(rb + (size_t)(c0 + c) * FEAT + d4);
            *(float4*)&Os[c][d4] = *(const float4*)(ob + (size_t)(c0 + c) * FEAT + d4);
        }
        __syncthreads();
        #pragma unroll 8
        for (int c = 0; c < 32; c++) {
            float a[8], b[8];
            #pragma unroll
            for (int i = 0; i < 8; i += 4) *(float4*)&a[i] = *(const float4*)&Rs[c][tr * 8 + i];
            #pragma unroll
            for (int j = 0; j < 8; j += 4) *(float4*)&b[j] = *(const float4*)&Os[c][tc * 8 + j];
            #pragma unroll
            for (int i = 0; i < 8; i++)
                #pragma unroll
                for (int j = 0; j < 8; j++) acc[i][j] += a[i] * b[j];
        }
        __syncthreads();
    }
    float* mb = MkF + (size_t)k * FEAT * FEAT;
    #pragma unroll
    for (int i = 0; i < 8; i++)
        #pragma unroll
        for (int j = 0; j < 8; j++)
            atomicAdd(mb + (size_t)(tr * 8 + i) * FEAT + tc * 8 + j, acc[i][j]);
}

// ---------------- Mk convert -> Wfin rows 128-255 --------------------------
__global__ __launch_bounds__(256) void mkcvt_kernel(const float* __restrict__ MkF,
                                                    __nv_bfloat16* __restrict__ WfH,
                                                    __nv_bfloat16* __restrict__ WfL) {
    const int k = blockIdx.x;
    const float* mb = MkF + (size_t)k * FEAT * FEAT;
    for (int idx = threadIdx.x; idx < FEAT * FEAT; idx += 256) {
        int e = idx >> 7, d = idx & 127;
        float v = mb[(size_t)d * FEAT + e];
        __nv_bfloat16 hi = __float2bfloat16(v);
        __nv_bfloat16 lo = __float2bfloat16(v - __bfloat162float(hi));
        size_t dst = (size_t)k * 256 * FEAT + (size_t)(128 + e) * FEAT + d;
        WfH[dst] = hi;
        WfL[dst] = lo;
    }
}

// ---------------- transpose + hi/lo split:  dst[n][k] = W[k][n] ------------
__global__ __launch_bounds__(256) void tsplit_kernel(const float* __restrict__ W,
                                                     __nv_bfloat16* __restrict__ Wh,
                                                     __nv_bfloat16* __restrict__ Wl,
                                                     int K, int N, int dstBatchStride) {
    const int batch = blockIdx.z;
    W += (size_t)batch * K * N;
    Wh += (size_t)batch * dstBatchStride;
    Wl += (size_t)batch * dstBatchStride;
    __shared__ float t[32][33];
    const int k0 = blockIdx.x * 32;
    const int n0 = blockIdx.y * 32;
    const int tx = threadIdx.x, ty = threadIdx.y;
    #pragma unroll
    for (int i = 0; i < 4; i++)
        t[ty + 8 * i][tx] = W[(size_t)(k0 + ty + 8 * i) * N + n0 + tx];
    __syncthreads();
    #pragma unroll
    for (int i = 0; i < 4; i++) {
        int n = n0 + ty + 8 * i;
        int k = k0 + tx;
        float v = t[tx][ty + 8 * i];
        __nv_bfloat16 hi = __float2bfloat16(v);
        __nv_bfloat16 lo = __float2bfloat16(v - __bfloat162float(hi));
        Wh[(size_t)n * K + k] = hi;
        Wl[(size_t)n * K + k] = lo;
    }
}

// ===========================================================================
// GEMM1 v2 (R6, best measured ~310us): cp.async 2-stage pipelined HMMA,
// BM=128, BN=256, 512 threads.
// ===========================================================================
#define G1_BUF 79872
#define G1_OF  0
#define G1_OAH 18432
#define G1_OAL 28672
#define G1_OWH 38912
#define G1_OWL 59392
#define G1_SMEM (2 * G1_BUF)
#define G1_NIT (D_IN / 32)

__global__ __launch_bounds__(512, 1) void gemm1_v2(
    const float* __restrict__ A0, const float* __restrict__ A1,
    const float* __restrict__ A2,
    const __nv_bfloat16* __restrict__ Bh, const __nv_bfloat16* __restrict__ Bl,
    const float* __restrict__ bias,
    __nv_bfloat16* __restrict__ Oh, __nv_bfloat16* __restrict__ Ol) {
    extern __shared__ char sm[];
    const uint32_t sb = smem_u32(sm);
    const int tid = threadIdx.x;
    const int wid = tid >> 5, lane = tid & 31;
    const int warpM = (wid & 3) * 32;
    const int warpN = (wid >> 2) * 64;
    const int m0 = blockIdx.x * 128;

    float acc[2][8][4];
    #pragma unroll
    for (int i = 0; i < 2; i++)
        #pragma unroll
        for (int j = 0; j < 8; j++)
            #pragma unroll
            for (int q = 0; q < 4; q++) acc[i][j][q] = 0.f;

    auto issue = [&](int it, int b) {
        const int k0 = it * 32;
        const float* Ap; int lda, kk;
        if (k0 < D_SUP)               { Ap = A0; lda = D_SUP;  kk = k0; }
        else if (k0 < D_SUP + D_ANOM) { Ap = A1; lda = D_ANOM; kk = k0 - D_SUP; }
        else                          { Ap = A2; lda = D_IND;  kk = k0 - D_SUP - D_ANOM; }
        const uint32_t bb = sb + b * G1_BUF;
        #pragma unroll
        for (int t = 0; t < 2; t++) {
            int idx = tid + t * 512;
            int row = idx >> 3, q = idx & 7;
            cp16(bb + G1_OF + row * 144 + q * 16,
                 Ap + (size_t)(m0 + row) * lda + kk + q * 4);
        }
        #pragma unroll
        for (int t = 0; t < 4; t++) {
            int idx = tid + t * 512;
            int half = idx >= 1024;
            int cc = idx & 1023;
            int row = cc >> 2, q = cc & 3;
            cp16(bb + (half ? G1_OWL : G1_OWH) + row * 80 + q * 16,
                 (half ? Bl : Bh) + (size_t)row * D_IN + it * 32 + q * 8);
        }
        CP_COMMIT();
    };

    issue(0, 0);

    for (int it = 0; it < G1_NIT; it++) {
        const int b = it & 1;
        const uint32_t bb = sb + b * G1_BUF;
        CP_WAIT0();
        __syncthreads();
        if (it + 1 < G1_NIT) issue(it + 1, b ^ 1);

        #pragma unroll
        for (int t = 0; t < 2; t++) {
            int idx = tid + t * 512;
            int row = idx >> 3, q = idx & 7;
            float4 v = *(const float4*)(sm + (size_t)b * G1_BUF + G1_OF + row * 144 + q * 16);
            __nv_bfloat16 hx = __float2bfloat16(v.x), hy = __float2bfloat16(v.y);
            __nv_bfloat16 hz = __float2bfloat16(v.z), hw = __float2bfloat16(v.w);
            __nv_bfloat162 h01 = {hx, hy}, h23 = {hz, hw};
            __nv_bfloat162 l01 = __floats2bfloat162_rn(v.x - __bfloat162float(hx),
                                                       v.y - __bfloat162float(hy));
            __nv_bfloat162 l23 = __floats2bfloat162_rn(v.z - __bfloat162float(hz),
                                                       v.w - __bfloat162float(hw));
            size_t off = (size_t)b * G1_BUF + (row * 40 + q * 4) * 2;
            *(__nv_bfloat162*)(sm + off + G1_OAH) = h01;
            *(__nv_bfloat162*)(sm + off + G1_OAH + 4) = h23;
            *(__nv_bfloat162*)(sm + off + G1_OAL) = l01;
            *(__nv_bfloat162*)(sm + off + G1_OAL + 4) = l23;
        }
        __syncthreads();

        const uint32_t aAh = bb + G1_OAH, aAl = bb + G1_OAL;
        const uint32_t aBh = bb + G1_OWH, aBl = bb + G1_OWL;
        #pragma unroll
        for (int kq = 0; kq < 2; kq++) {
            uint32_t a_h[2][4], a_l[2][4], bfr[8][2];
            const int colh = kq * 16 + ((lane >> 4) << 3);
            #pragma unroll
            for (int mt = 0; mt < 2; mt++) {
                int row = warpM + mt * 16 + (lane & 15);
                ldsm4(a_h[mt], aAh + (uint32_t)(row * 40 + colh) * 2);
                ldsm4(a_l[mt], aAl + (uint32_t)(row * 40 + colh) * 2);
            }
            #pragma unroll
            for (int nt2 = 0; nt2 < 4; nt2++) {
                int row = warpN + nt2 * 16 + (lane & 15);
                uint32_t r[4];
                ldsm4(r, aBh + (uint32_t)(row * 40 + colh) * 2);
                bfr[2 * nt2][0] = r[0]; bfr[2 * nt2][1] = r[2];
                bfr[2 * nt2 + 1][0] = r[1]; bfr[2 * nt2 + 1][1] = r[3];
            }
            #pragma unroll
            for (int mt = 0; mt < 2; mt++)
                #pragma unroll
                for (int nt = 0; nt < 8; nt++) mma_bf16(acc[mt][nt], a_h[mt], bfr[nt]);
            #pragma unroll
            for (int mt = 0; mt < 2; mt++)
                #pragma unroll
                for (int nt = 0; nt < 8; nt++) mma_bf16(acc[mt][nt], a_l[mt], bfr[nt]);
            #pragma unroll
            for (int nt2 = 0; nt2 < 4; nt2++) {
                int row = warpN + nt2 * 16 + (lane & 15);
                uint32_t r[4];
                ldsm4(r, aBl + (uint32_t)(row * 40 + colh) * 2);
                bfr[2 * nt2][0] = r[0]; bfr[2 * nt2][1] = r[2];
                bfr[2 * nt2 + 1][0] = r[1]; bfr[2 * nt2 + 1][1] = r[3];
            }
            #pragma unroll
            for (int mt = 0; mt < 2; mt++)
                #pragma unroll
                for (int nt = 0; nt < 8; nt++) mma_bf16(acc[mt][nt], a_h[mt], bfr[nt]);
        }
    }

    #pragma unroll
    for (int mt = 0; mt < 2; mt++) {
        const int r0 = m0 + warpM + mt * 16 + (lane >> 2);
        #pragma unroll
        for (int nt = 0; nt < 8; nt++) {
            const int cc = warpN + nt * 8 + ((lane & 3) << 1);
            float2 bv = *(const float2*)(bias + cc);
            float v00 = fmaxf(acc[mt][nt][0] + bv.x, 0.f);
            float v01 = fmaxf(acc[mt][nt][1] + bv.y, 0.f);
            float v10 = fmaxf(acc[mt][nt][2] + bv.x, 0.f);
            float v11 = fmaxf(acc[mt][nt][3] + bv.y, 0.f);
            __nv_bfloat16 h00 = __float2bfloat16(v00), h01 = __float2bfloat16(v01);
            __nv_bfloat16 h10 = __float2bfloat16(v10), h11 = __float2bfloat16(v11);
            __nv_bfloat162 hi0 = {h00, h01}, hi1 = {h10, h11};
            __nv_bfloat162 lo0 = __floats2bfloat162_rn(v00 - __bfloat162float(h00),
                                                       v01 - __bfloat162float(h01));
            __nv_bfloat162 lo1 = __floats2bfloat162_rn(v10 - __bfloat162float(h10),
                                                       v11 - __bfloat162float(h11));
            *(__nv_bfloat162*)(Oh + (size_t)r0 * H1 + cc) = hi0;
            *(__nv_bfloat162*)(Ol + (size_t)r0 * H1 + cc) = lo0;
            *(__nv_bfloat162*)(Oh + (size_t)(r0 + 8) * H1 + cc) = hi1;
            *(__nv_bfloat162*)(Ol + (size_t)(r0 + 8) * H1 + cc) = lo1;
        }
    }
}

// ===========================================================================
// Fused tail (R6, best measured): GEMM2 + 12 layers + final, cp.async prefetch.
// ===========================================================================
#define LDA 136
#define TAIL_SMEM ((128 * LDA * 2 + 256 * LDA * 2) * 2 + 256 * 4)

__global__ __launch_bounds__(512, 1) void fused_tail(
    const __nv_bfloat16* __restrict__ h1h, const __nv_bfloat16* __restrict__ h1l,
    const __nv_bfloat16* __restrict__ Wh2, const __nv_bfloat16* __restrict__ Wl2,
    const float* __restrict__ b2,
    const __nv_bfloat16* __restrict__ WhC, const __nv_bfloat16* __restrict__ WlC,
    const float* __restrict__ consB,
    const __nv_bfloat16* __restrict__ WfH, const __nv_bfloat16* __restrict__ WfL,
    const float* __restrict__ retB, const float* __restrict__ aw,
    float* __restrict__ out) {
    extern __shared__ __nv_bfloat16 smt[];
    __nv_bfloat16* sAh = smt;
    __nv_bfloat16* sAl = sAh + 128 * LDA;
    __nv_bfloat16* sWh = sAl + 128 * LDA;
    __nv_bfloat16* sWl = sWh + 256 * LDA;
    float* wsum = (float*)(sWl + 256 * LDA);
    float* saw  = wsum + 128;

    const int tid = threadIdx.x;
    const int wid = tid >> 5, lane = tid & 31;
    const int wm = wid & 3;
    const int wn = wid >> 2;
    const int m0 = blockIdx.x * 128;

    const uint32_t aAh = smem_u32(sAh), aAl = smem_u32(sAl);
    const uint32_t aWh = smem_u32(sWh), aWl = smem_u32(sWl);

    auto issueW = [&](const __nv_bfloat16* srcH, const __nv_bfloat16* srcL,
                      int srcStride, int slot) {
        #pragma unroll
        for (int t = 0; t < 8; t++) {
            int idx = tid + t * 512;
            int half = idx >= 2048;
            int cc = idx & 2047;
            int row = cc >> 4, q = cc & 15;
            const __nv_bfloat16* src = (half ? srcL : srcH) + (size_t)row * srcStride + q * 8;
            cp16((half ? aWl : aWh) + (uint32_t)((slot * 128 + row) * LDA + q * 8) * 2, src);
        }
        CP_COMMIT();
    };
    auto issueAct = [&](int kc) {
        #pragma unroll
        for (int t = 0; t < 8; t++) {
            int idx = tid + t * 512;
            int half = idx >= 2048;
            int cc = idx & 2047;
            int row = cc >> 4, q = cc & 15;
            const __nv_bfloat16* src = (half ? h1l : h1h)
                + (size_t)(m0 + row) * H1 + kc * 128 + q * 8;
            cp16((half ? aAl : aAh) + (uint32_t)(row * LDA + q * 8) * 2, src);
        }
        CP_COMMIT();
    };
    auto issueFin = [&](int k) {
        #pragma unroll
        for (int t = 0; t < 16; t++) {
            int idx = tid + t * 512;
            int half = idx >= 4096;
            int cc = idx & 4095;
            int row = cc >> 4, q = cc & 15;
            const __nv_bfloat16* src = (half ? WfL : WfH)
                + (size_t)k * 256 * FEAT + (size_t)row * FEAT + q * 8;
            cp16((half ? aWl : aWh) + (uint32_t)(row * LDA + q * 8) * 2, src);
        }
        CP_COMMIT();
    };

    auto mma128 = [&](float acc4[2][4][4], int slot) {
        const uint32_t base = (uint32_t)(slot * 128 * LDA) * 2;
        #pragma unroll
        for (int ch = 0; ch < 8; ch++) {
            const int colh = ch * 16 + ((lane >> 4) << 3);
            uint32_t a_h[2][4], a_l[2][4], bfr[4][2];
            #pragma unroll
            for (int mt = 0; mt < 2; mt++) {
                int row = wm * 32 + mt * 16 + (lane & 15);
                ldsm4(a_h[mt], aAh + (uint32_t)(row * LDA + colh) * 2);
                ldsm4(a_l[mt], aAl + (uint32_t)(row * LDA + colh) * 2);
            }
            #pragma unroll
            for (int nt2 = 0; nt2 < 2; nt2++) {
                int row = wn * 32 + nt2 * 16 + (lane & 15);
                uint32_t r[4];
                ldsm4(r, aWh + base + (uint32_t)(row * LDA + colh) * 2);
                bfr[2 * nt2][0] = r[0]; bfr[2 * nt2][1] = r[2];
                bfr[2 * nt2 + 1][0] = r[1]; bfr[2 * nt2 + 1][1] = r[3];
            }
            #pragma unroll
            for (int mt = 0; mt < 2; mt++)
                #pragma unroll
                for (int nt = 0; nt < 4; nt++) mma_bf16(acc4[mt][nt], a_h[mt], bfr[nt]);
            #pragma unroll
            for (int mt = 0; mt < 2; mt++)
                #pragma unroll
                for (int nt = 0; nt < 4; nt++) mma_bf16(acc4[mt][nt], a_l[mt], bfr[nt]);
            #pragma unroll
            for (int nt2 = 0; nt2 < 2; nt2++) {
                int row = wn * 32 + nt2 * 16 + (lane & 15);
                uint32_t r[4];
                ldsm4(r, aWl + base + (uint32_t)(row * LDA + colh) * 2);
                bfr[2 * nt2][0] = r[0]; bfr[2 * nt2][1] = r[2];
                bfr[2 * nt2 + 1][0] = r[1]; bfr[2 * nt2 + 1][1] = r[3];
            }
            #pragma unroll
            for (int mt = 0; mt < 2; mt++)
                #pragma unroll
                for (int nt = 0; nt < 4; nt++) mma_bf16(acc4[mt][nt], a_h[mt], bfr[nt]);
        }
    };
    auto epilogue = [&](float acc4[2][4][4], const float* biasp) {
        #pragma unroll
        for (int mt = 0; mt < 2; mt++) {
            const int row = wm * 32 + mt * 16 + (lane >> 2);
            #pragma unroll
            for (int nt = 0; nt < 4; nt++) {
                const int col = wn * 32 + nt * 8 + ((lane & 3) << 1);
                float2 bv = *(const float2*)(biasp + col);
                float v00 = fmaxf(acc4[mt][nt][0] + bv.x, 0.f);
                float v01 = fmaxf(acc4[mt][nt][1] + bv.y, 0.f);
                float v10 = fmaxf(acc4[mt][nt][2] + bv.x, 0.f);
                float v11 = fmaxf(acc4[mt][nt][3] + bv.y, 0.f);
                __nv_bfloat16 h00 = __float2bfloat16(v00), h01 = __float2bfloat16(v01);
                __nv_bfloat16 h10 = __float2bfloat16(v10), h11 = __float2bfloat16(v11);
                __nv_bfloat162 hi0 = {h00, h01}, hi1 = {h10, h11};
                __nv_bfloat162 lo0 = __floats2bfloat162_rn(v00 - __bfloat162float(h00),
                                                           v01 - __bfloat162float(h01));
                __nv_bfloat162 lo1 = __floats2bfloat162_rn(v10 - __bfloat162float(h10),
                                                           v11 - __bfloat162float(h11));
                *(__nv_bfloat162*)(sAh + row * LDA + col) = hi0;
                *(__nv_bfloat162*)(sAl + row * LDA + col) = lo0;
                *(__nv_bfloat162*)(sAh + (row + 8) * LDA + col) = hi1;
                *(__nv_bfloat162*)(sAl + (row + 8) * LDA + col) = lo1;
            }
        }
    };

    if (tid < 128) saw[tid] = aw[m0 + tid];

    issueW(Wh2, Wl2, H1, 0);
    issueAct(0);
    {
        #pragma unroll
        for (int t = 0; t < 8; t++) {
            int idx = tid + t * 512;
            int half = idx >= 2048;
            int cc = idx & 2047;
            int row = cc >> 4, q = cc & 15;
            const __nv_bfloat16* src = (half ? Wl2 : Wh2) + (size_t)row * H1 + 128 + q * 8;
            cp16((half ? aWl : aWh) + (uint32_t)((128 + row) * LDA + q * 8) * 2, src);
        }
        CP_COMMIT();
    }

    float acc4[2][4][4];
    #pragma unroll
    for (int i = 0; i < 2; i++)
        #pragma unroll
        for (int j = 0; j < 4; j++)
            #pragma unroll
            for (int q = 0; q < 4; q++) acc4[i][j][q] = 0.f;

    CP_WAIT1();
    __syncthreads();
    mma128(acc4, 0);
    __syncthreads();
    issueAct(1);
    issueW(WhC, WlC, FEAT, 0);
    CP_WAIT1();
    __syncthreads();
    mma128(acc4, 1);
    __syncthreads();
    epilogue(acc4, b2);
    __syncthreads();

    for (int l = 0; l < DEPTH; l++) {
        if (l + 1 < DEPTH)
            issueW(WhC + (size_t)(l + 1) * FEAT * FEAT,
                   WlC + (size_t)(l + 1) * FEAT * FEAT, FEAT, (l + 1) & 1);
        if (l + 1 < DEPTH) { CP_WAIT1(); } else { CP_WAIT0(); }
        __syncthreads();
        #pragma unroll
        for (int i = 0; i < 2; i++)
            #pragma unroll
            for (int j = 0; j < 4; j++)
                #pragma unroll
                for (int q = 0; q < 4; q++) acc4[i][j][q] = 0.f;
        mma128(acc4, l & 1);
        __syncthreads();
        epilogue(acc4, consB + (size_t)l * FEAT);
        __syncthreads();
    }

    issueFin(0);
    CP_WAIT0();
    const float cfac = 0.42f * 1.8f / (float)CAP;
    for (int k = 0; k < NCOND; k++) {
        __syncthreads();
        if (tid < 128) wsum[tid] = 0.f;

        float acc8[2][8][4];
        #pragma unroll
        for (int i = 0; i < 2; i++)
            #pragma unroll
            for (int j = 0; j < 8; j++)
                #pragma unroll
                for (int q = 0; q < 4; q++) acc8[i][j][q] = 0.f;

        #pragma unroll
        for (int ch = 0; ch < 8; ch++) {
            const int colh = ch * 16 + ((lane >> 4) << 3);
            uint32_t a_h[2][4], a_l[2][4], bfr[8][2];
            #pragma unroll
            for (int mt = 0; mt < 2; mt++) {
                int row = wm * 32 + mt * 16 + (lane & 15);
                ldsm4(a_h[mt], aAh + (uint32_t)(row * LDA + colh) * 2);
                ldsm4(a_l[mt], aAl + (uint32_t)(row * LDA + colh) * 2);
            }
            #pragma unroll
            for (int nt2 = 0; nt2 < 4; nt2++) {
                int row = wn * 64 + nt2 * 16 + (lane & 15);
                uint32_t r[4];
                ldsm4(r, aWh + (uint32_t)(row * LDA + colh) * 2);
                bfr[2 * nt2][0] = r[0]; bfr[2 * nt2][1] = r[2];
                bfr[2 * nt2 + 1][0] = r[1]; bfr[2 * nt2 + 1][1] = r[3];
            }
            #pragma unroll
            for (int mt = 0; mt < 2; mt++)
                #pragma unroll
                for (int nt = 0; nt < 8; nt++) mma_bf16(acc8[mt][nt], a_h[mt], bfr[nt]);
            #pragma unroll
            for (int mt = 0; mt < 2; mt++)
                #pragma unroll
                for (int nt = 0; nt < 8; nt++) mma_bf16(acc8[mt][nt], a_l[mt], bfr[nt]);
            #pragma unroll
            for (int nt2 = 0; nt2 < 4; nt2++) {
                int row = wn * 64 + nt2 * 16 + (lane & 15);
                uint32_t r[4];
                ldsm4(r, aWl + (uint32_t)(row * LDA + colh) * 2);
                bfr[2 * nt2][0] = r[0]; bfr[2 * nt2][1] = r[2];
                bfr[2 * nt2 + 1][0] = r[1]; bfr[2 * nt2 + 1][1] = r[3];
            }
            #pragma unroll
            for (int mt = 0; mt < 2; mt++)
                #pragma unroll
                for (int nt = 0; nt < 8; nt++) mma_bf16(acc8[mt][nt], a_h[mt], bfr[nt]);
        }
        __syncthreads();
        if (k + 1 < NCOND) issueFin(k + 1);

        if (wn >= 2) {
            #pragma unroll
            for (int mt = 0; mt < 2; mt++) {
                const int r1 = wm * 32 + mt * 16 + (lane >> 2);
                float p1 = 0.f, p2 = 0.f;
                #pragma unroll
                for (int nt = 0; nt < 8; nt++) {
                    const int e0 = (wn - 2) * 64 + nt * 8 + ((lane & 3) << 1);
                    float m00 = __bfloat162float(sAh[r1 * LDA + e0]) +
                                __bfloat162float(sAl[r1 * LDA + e0]);
                    float m01 = __bfloat162float(sAh[r1 * LDA + e0 + 1]) +
                                __bfloat162float(sAl[r1 * LDA + e0 + 1]);
                    float m10 = __bfloat162float(sAh[(r1 + 8) * LDA + e0]) +
                                __bfloat162float(sAl[(r1 + 8) * LDA + e0]);
                    float m11 = __bfloat162float(sAh[(r1 + 8) * LDA + e0 + 1]) +
                                __bfloat162float(sAl[(r1 + 8) * LDA + e0 + 1]);
                    p1 += acc8[mt][nt][0] * m00 + acc8[mt][nt][1] * m01;
                    p2 += acc8[mt][nt][2] * m10 + acc8[mt][nt][3] * m11;
                }
                atomicAdd(&wsum[r1], p1);
                atomicAdd(&wsum[r1 + 8], p2);
            }
        }
        __syncthreads();
        if (tid < 128) wsum[tid] = wsum[tid] * cfac + 0.3f * saw[tid];
        __syncthreads();

        if (wn < 2) {
            #pragma unroll
            for (int mt = 0; mt < 2; mt++) {
                const int rl = wm * 32 + mt * 16 + (lane >> 2);
                const float w1 = wsum[rl], w2 = wsum[rl + 8];
                #pragma unroll
                for (int nt = 0; nt < 8; nt++) {
                    const int col = wn * 64 + nt * 8 + ((lane & 3) << 1);
                    float2 bv = *(const float2*)(retB + (size_t)k * FEAT + col);
                    size_t base1 = (size_t)(m0 + rl) * (NCOND * FEAT) + (size_t)k * FEAT + col;
                    size_t base2 = (size_t)(m0 + rl + 8) * (NCOND * FEAT) + (size_t)k * FEAT + col;
                    *(float2*)(out + base1) = make_float2((acc8[mt][nt][0] + bv.x) * w1,
                                                          (acc8[mt][nt][1] + bv.y) * w1);
                    *(float2*)(out + base2) = make_float2((acc8[mt][nt][2] + bv.x) * w2,
                                                          (acc8[mt][nt][3] + bv.y) * w2);
                }
            }
        }
        if (k + 1 < NCOND) CP_WAIT0();
    }
}

// ===========================================================================
extern "C" void kernel_launch(void* const* d_in, const int* in_sizes, int n_in,
                              void* d_out, int out_size) {
    const float* sup  = (const float*)d_in[0];
    const float* anom = (const float*)d_in[1];
    const float* ind  = (const float*)d_in[2];
    const float* ipW1 = (const float*)d_in[3];
    const float* ipb1 = (const float*)d_in[4];
    const float* ipW2 = (const float*)d_in[5];
    const float* ipb2 = (const float*)d_in[6];
    const float* consW = (const float*)d_in[7];
    const float* consB = (const float*)d_in[8];
    const float* refp = (const float*)d_in[9];
    const float* objp = (const float*)d_in[10];
    const float* retW = (const float*)d_in[11];
    const float* retB = (const float*)d_in[12];
    float* out = (float*)d_out;

    __nv_bfloat16 *Wh1, *Wl1, *Wh2, *Wl2, *WhC, *WlC, *h1h, *h1l, *WfH, *WfL;
    float *aw, *MkF;
    cudaGetSymbolAddress((void**)&Wh1, g_Wh1);
    cudaGetSymbolAddress((void**)&Wl1, g_Wl1);
    cudaGetSymbolAddress((void**)&Wh2, g_Wh2);
    cudaGetSymbolAddress((void**)&Wl2, g_Wl2);
    cudaGetSymbolAddress((void**)&WhC, g_WhC);
    cudaGetSymbolAddress((void**)&WlC, g_WlC);
    cudaGetSymbolAddress((void**)&h1h, g_h1h);
    cudaGetSymbolAddress((void**)&h1l, g_h1l);
    cudaGetSymbolAddress((void**)&WfH, g_WfinH);
    cudaGetSymbolAddress((void**)&WfL, g_WfinL);
    cudaGetSymbolAddress((void**)&aw, g_aw);
    cudaGetSymbolAddress((void**)&MkF, g_MkF);

    cudaFuncSetAttribute(gemm1_v2, cudaFuncAttributeMaxDynamicSharedMemorySize, G1_SMEM);
    cudaFuncSetAttribute(fused_tail, cudaFuncAttributeMaxDynamicSharedMemorySize, TAIL_SMEM);

    // ncu captures kernel_launch's 4th launch (harness issues 2 before ours).
    tsplit_kernel<<<dim3(D_IN / 32, H1 / 32, 1), dim3(32, 8)>>>(ipW1, Wh1, Wl1, D_IN, H1, H1 * D_IN); // 1
    aw_kernel<<<BB * 32 / 256, 256>>>(anom, aw);                                      // 2
    mkzero_kernel<<<NCOND * FEAT * FEAT / 1024, 256>>>(MkF);                          // 3
    gemm1_v2<<<BB / 128, 512, G1_SMEM>>>(sup, anom, ind, Wh1, Wl1, ipb1, h1h, h1l);   // 4 (profiled)
    mkpart_kernel<<<dim3(NCOND, 4), 256>>>(refp, objp, MkF);                          // 5
    mkcvt_kernel<<<NCOND, 256>>>(MkF, WfH, WfL);                                      // 6
    tsplit_kernel<<<dim3(H1 / 32, FEAT / 32, 1), dim3(32, 8)>>>(ipW2, Wh2, Wl2, H1, FEAT, FEAT * H1); // 7
    tsplit_kernel<<<dim3(FEAT / 32, FEAT / 32, DEPTH), dim3(32, 8)>>>(consW, WhC, WlC, FEAT, FEAT, FEAT * FEAT); // 8
    tsplit_kernel<<<dim3(FEAT / 32, FEAT / 32, NCOND), dim3(32, 8)>>>(retW, WfH, WfL, FEAT, FEAT, 256 * FEAT);   // 9
    fused_tail<<<BB / 128, 512, TAIL_SMEM>>>(
        h1h, h1l, Wh2, Wl2, ipb2, WhC, WlC, consB, WfH, WfL, retB, aw, out);          // 10
}